// round 1
// baseline (speedup 1.0000x reference)
#include <cuda_runtime.h>
#include <cstdint>
#include <cstdio>

// 2-layer LSTM, NS=51, B=8192, T=2048, input dim 1, output [B, T] fp32.
// Persistent warp-synchronous kernel: 128 CTAs x 256 threads, each warp owns
// 8 batch rows for all 2048 timesteps. All weights in smem, pre-transposed.
// GEMM uses packed fma.rn.f32x2 (2 batch rows per 64-bit register).

#define NS       51
#define G4       204         // 4*NS gates
#define GP       208         // gate stride in smem (pad)
#define T_LEN    2048
#define BSZ      8192
#define WARPS    8
#define RPW      8           // rows per warp
#define ROWS     (WARPS*RPW) // 64 rows per block
#define HSTRIDE  10          // padded row stride for h buffer (bank-conflict-free-ish, 8B aligned)
#define HROWS    103         // rows 0..50 = h1, 51..101 = h2, 102 = x_t
#define NCELLMAX 13          // ceil(8*51/32)

typedef unsigned long long u64;

struct Smem {
    float W1t[52 * GP + 32];    // [k][gate]; k=0..50 -> W_hh1^T, k=51 -> W_ih1 col; zero-padded
    float W2t[102 * GP + 32];   // k=0..50 -> W_ih2^T (input h1new), k=51..101 -> W_hh2^T
    float b1[224];              // b_ih1 + b_hh1, zero-padded
    float b2[224];
    float wlin[64];
    float h12[WARPS][HROWS][HSTRIDE]; // per-warp state: h1|h2|x, rows-in-warp minor
    float gsh[WARPS][RPW][GP];        // per-warp gate staging
};

__device__ __forceinline__ u64 pk2(float a, float b) {
    u64 r; asm("mov.b64 %0, {%1,%2};" : "=l"(r) : "f"(a), "f"(b)); return r;
}
__device__ __forceinline__ float2 upk2(u64 v) {
    float2 r; asm("mov.b64 {%0,%1}, %2;" : "=f"(r.x), "=f"(r.y) : "l"(v)); return r;
}
__device__ __forceinline__ void fma2(u64& d, u64 a, u64 b) {
    asm("fma.rn.f32x2 %0, %1, %2, %0;" : "+l"(d) : "l"(a), "l"(b));
}
__device__ __forceinline__ float sigf(float x) {
    return __fdividef(1.0f, 1.0f + __expf(-x));
}
__device__ __forceinline__ float tanhf_(float x) {
    // tanh(x) = 2*sigmoid(2x) - 1
    return fmaf(2.0f, sigf(2.0f * x), -1.0f);
}

// One k-slice of the gate GEMM: 7 gate-groups x 4 row-pairs of f32x2 FMAs.
#define GEMM_STEP(WROW, HR)                                            \
    do {                                                               \
        const float* hr_ = (HR);                                      \
        u64 hp0 = *(const u64*)(hr_ + 0);                             \
        u64 hp1 = *(const u64*)(hr_ + 2);                             \
        u64 hp2 = *(const u64*)(hr_ + 4);                             \
        u64 hp3 = *(const u64*)(hr_ + 6);                             \
        const float* wr_ = (WROW);                                    \
        _Pragma("unroll")                                             \
        for (int j = 0; j < 7; j++) {                                 \
            float wv = wr_[j * 32];                                   \
            u64 wp = pk2(wv, wv);                                     \
            fma2(acc[j][0], hp0, wp);                                 \
            fma2(acc[j][1], hp1, wp);                                 \
            fma2(acc[j][2], hp2, wp);                                 \
            fma2(acc[j][3], hp3, wp);                                 \
        }                                                              \
    } while (0)

__global__ __launch_bounds__(256, 1)
void lstm2_kernel(const float* __restrict__ x,
                  const float* __restrict__ W_ih1, const float* __restrict__ W_hh1,
                  const float* __restrict__ b_ih1, const float* __restrict__ b_hh1,
                  const float* __restrict__ W_ih2, const float* __restrict__ W_hh2,
                  const float* __restrict__ b_ih2, const float* __restrict__ b_hh2,
                  const float* __restrict__ W_lin, const float* __restrict__ b_lin,
                  float* __restrict__ out)
{
    extern __shared__ Smem smem_raw[];
    Smem& sm = smem_raw[0];
    const int tid = threadIdx.x;

    // ---------------- one-time smem setup (block-wide) ----------------
    for (int idx = tid; idx < 52 * GP + 32; idx += 256) {
        int k = idx / GP, g = idx - k * GP;
        float v = 0.0f;
        if (idx < 52 * GP && g < G4)
            v = (k < 51) ? W_hh1[g * NS + k] : W_ih1[g];
        sm.W1t[idx] = v;
    }
    for (int idx = tid; idx < 102 * GP + 32; idx += 256) {
        int k = idx / GP, g = idx - k * GP;
        float v = 0.0f;
        if (idx < 102 * GP && g < G4)
            v = (k < 51) ? W_ih2[g * NS + k] : W_hh2[g * NS + (k - 51)];
        sm.W2t[idx] = v;
    }
    for (int idx = tid; idx < 224; idx += 256) {
        float v1 = 0.0f, v2 = 0.0f;
        if (idx < G4) {
            v1 = b_ih1[idx] + b_hh1[idx];
            v2 = b_ih2[idx] + b_hh2[idx];
        }
        sm.b1[idx] = v1;
        sm.b2[idx] = v2;
    }
    if (tid < 64) sm.wlin[tid] = (tid < NS) ? W_lin[tid] : 0.0f;
    for (int idx = tid; idx < WARPS * HROWS * HSTRIDE; idx += 256)
        (&sm.h12[0][0][0])[idx] = 0.0f;
    __syncthreads();

    // ---------------- per-thread init ----------------
    const int warp = tid >> 5, lane = tid & 31;
    float* __restrict__ h  = &sm.h12[warp][0][0];   // [HROWS][HSTRIDE]
    float* __restrict__ gs = &sm.gsh[warp][0][0];   // [RPW][GP]
    const int rbase = blockIdx.x * ROWS + warp * RPW;
    const float blin = b_lin[0];

    u64 b1p[7], b2p[7];
#pragma unroll
    for (int j = 0; j < 7; j++) {
        float v1 = sm.b1[j * 32 + lane]; b1p[j] = pk2(v1, v1);
        float v2 = sm.b2[j * 32 + lane]; b2p[j] = pk2(v2, v2);
    }

    // elementwise cell map: cells = 8 rows x 51 units per warp
    float c1v[NCELLMAX], c2v[NCELLMAX];
    int cr[NCELLMAX], cn[NCELLMAX];
#pragma unroll
    for (int i = 0; i < NCELLMAX; i++) {
        int cell = lane + 32 * i;
        int r = cell / 51;
        cr[i] = r;
        cn[i] = cell - r * 51;
        c1v[i] = 0.0f;
        c2v[i] = 0.0f;
    }

    float xreg = (lane < RPW) ? x[(rbase + lane) * T_LEN] : 0.0f;

    // ---------------- time loop (warp-synchronous) ----------------
    for (int t = 0; t < T_LEN; t++) {
        if (lane < RPW) h[102 * HSTRIDE + lane] = xreg;
        __syncwarp();
        if (lane < RPW && t + 1 < T_LEN)
            xreg = x[(rbase + lane) * T_LEN + t + 1];

        u64 acc[7][4];

        // ===== layer 1 gates: W_hh1 @ h1 + W_ih1 * x + b =====
#pragma unroll
        for (int j = 0; j < 7; j++)
#pragma unroll
            for (int rp = 0; rp < 4; rp++) acc[j][rp] = b1p[j];

#pragma unroll 3
        for (int k = 0; k < 51; k++)
            GEMM_STEP(sm.W1t + k * GP + lane, h + k * HSTRIDE);
        GEMM_STEP(sm.W1t + 51 * GP + lane, h + 102 * HSTRIDE);  // x term

#pragma unroll
        for (int j = 0; j < 7; j++) {
            int g = j * 32 + lane;
            if (g < G4) {
#pragma unroll
                for (int rp = 0; rp < 4; rp++) {
                    float2 v = upk2(acc[j][rp]);
                    gs[(2 * rp) * GP + g]     = v.x;
                    gs[(2 * rp + 1) * GP + g] = v.y;
                }
            }
        }
        __syncwarp();

        // ===== layer 1 elementwise =====
#pragma unroll
        for (int i = 0; i < NCELLMAX; i++) {
            int cell = lane + 32 * i;
            if (cell < RPW * NS) {
                const float* gr = gs + cr[i] * GP;
                int n = cn[i];
                float ii = gr[n], ff = gr[51 + n], gg = gr[102 + n], oo = gr[153 + n];
                float c = sigf(ff) * c1v[i] + sigf(ii) * tanhf_(gg);
                c1v[i] = c;
                h[n * HSTRIDE + cr[i]] = sigf(oo) * tanhf_(c);  // h1_new -> rows 0..50
            }
        }
        __syncwarp();

        // ===== layer 2 gates: W_ih2 @ h1_new + W_hh2 @ h2 + b =====
#pragma unroll
        for (int j = 0; j < 7; j++)
#pragma unroll
            for (int rp = 0; rp < 4; rp++) acc[j][rp] = b2p[j];

#pragma unroll 3
        for (int k = 0; k < 102; k++)
            GEMM_STEP(sm.W2t + k * GP + lane, h + k * HSTRIDE);

#pragma unroll
        for (int j = 0; j < 7; j++) {
            int g = j * 32 + lane;
            if (g < G4) {
#pragma unroll
                for (int rp = 0; rp < 4; rp++) {
                    float2 v = upk2(acc[j][rp]);
                    gs[(2 * rp) * GP + g]     = v.x;
                    gs[(2 * rp + 1) * GP + g] = v.y;
                }
            }
        }
        __syncwarp();

        // ===== layer 2 elementwise =====
#pragma unroll
        for (int i = 0; i < NCELLMAX; i++) {
            int cell = lane + 32 * i;
            if (cell < RPW * NS) {
                const float* gr = gs + cr[i] * GP;
                int n = cn[i];
                float ii = gr[n], ff = gr[51 + n], gg = gr[102 + n], oo = gr[153 + n];
                float c = sigf(ff) * c2v[i] + sigf(ii) * tanhf_(gg);
                c2v[i] = c;
                h[(51 + n) * HSTRIDE + cr[i]] = sigf(oo) * tanhf_(c);  // h2_new -> rows 51..101
            }
        }
        __syncwarp();

        // ===== output projection y = h2 @ W_lin^T + b_lin =====
        if (lane < RPW) {
            float y = blin;
#pragma unroll 3
            for (int n = 0; n < NS; n++)
                y = fmaf(h[(51 + n) * HSTRIDE + lane], sm.wlin[n], y);
            out[(size_t)(rbase + lane) * T_LEN + t] = y;
        }
        __syncwarp();
    }
}

extern "C" void kernel_launch(void* const* d_in, const int* in_sizes, int n_in,
                              void* d_out, int out_size) {
    const float* x     = (const float*)d_in[0];
    const float* W_ih1 = (const float*)d_in[1];
    const float* W_hh1 = (const float*)d_in[2];
    const float* b_ih1 = (const float*)d_in[3];
    const float* b_hh1 = (const float*)d_in[4];
    const float* W_ih2 = (const float*)d_in[5];
    const float* W_hh2 = (const float*)d_in[6];
    const float* b_ih2 = (const float*)d_in[7];
    const float* b_hh2 = (const float*)d_in[8];
    const float* W_lin = (const float*)d_in[9];
    const float* b_lin = (const float*)d_in[10];
    float* out = (float*)d_out;

    cudaFuncSetAttribute(lstm2_kernel,
                         cudaFuncAttributeMaxDynamicSharedMemorySize,
                         (int)sizeof(Smem));
    lstm2_kernel<<<BSZ / ROWS, 256, sizeof(Smem)>>>(
        x, W_ih1, W_hh1, b_ih1, b_hh1,
        W_ih2, W_hh2, b_ih2, b_hh2,
        W_lin, b_lin, out);
}

// round 2
// speedup vs baseline: 1.1117x; 1.1117x over previous
#include <cuda_runtime.h>

// 2-layer LSTM, NS=51, B=8192, T=2048, out [B,T] fp32.
// Persistent warp-synchronous kernel: 147 CTAs x 256 thr, each warp owns 7 rows.
// GEMM packs K-PAIRS into fma.rn.f32x2: acc = {sum_even_k, sum_odd_k}.
// Weights pre-interleaved as u64 {w[2kp][g], w[2kp+1][g]} -> mov-free weight operand.
// h stored k-contiguous per row -> LDS.128 broadcast quad gives mov-free h operand.

#define NS    51
#define G4    204
#define TLEN  2048
#define BSZ   8192
#define WARPS 8
#define RPW   7
#define ROWS  56            // WARPS*RPW
#define GRID  147           // ceil(8192/56)
#define KQ1   13            // layer1: K=52 -> 13 quads
#define KQ2   26            // layer2: K=104 (51 h1 | pad | 51 h2 | pad) -> 26 quads
#define NCELL 12            // ceil(7*51/32)

typedef unsigned long long u64;

struct Smem {
    u64 Wp1[26 * G4 + 32];   // [kp][g] = {W1(2kp,g), W1(2kp+1,g)}; k=51 -> W_ih1
    u64 Wp2[52 * G4 + 32];   // k<51: W_ih2; k==51: 0; 52..102: W_hh2; k==103: 0
    u64 b1p[224];            // {b_ih+b_hh, 0}, zero padded
    u64 b2p[224];
    u64 wlinp[32];           // {W_lin[2n], W_lin[2n+1]}
    float hA[WARPS][RPW][52];    // layer1 input: h1 (0..50), x (51)
    float hB[WARPS][RPW][104];   // layer2 input: h1new (0..50), 0, h2 (52..102), 0
    float gs[WARPS][RPW][G4];    // gate staging
};

__device__ __forceinline__ u64 pk2(float a, float b) {
    u64 r; asm("mov.b64 %0, {%1,%2};" : "=l"(r) : "f"(a), "f"(b)); return r;
}
__device__ __forceinline__ float2 upk2(u64 v) {
    float2 r; asm("mov.b64 {%0,%1}, %2;" : "=f"(r.x), "=f"(r.y) : "l"(v)); return r;
}
__device__ __forceinline__ void fma2(u64& d, u64 a, u64 b) {
    asm("fma.rn.f32x2 %0, %1, %2, %0;" : "+l"(d) : "l"(a), "l"(b));
}
__device__ __forceinline__ float sigf(float x) {
    return __fdividef(1.0f, 1.0f + __expf(-x));
}
__device__ __forceinline__ float tanhf_(float x) {
    return fmaf(2.0f, sigf(2.0f * x), -1.0f);
}

// One layer's gate GEMM. HSTR = row stride of H in floats; NQ = #k-quads.
#define GEMM_LAYER(NQ, WPTR, HPTR, HSTR, BPTR)                              \
    do {                                                                    \
        _Pragma("unroll")                                                   \
        for (int j = 0; j < 7; j++) {                                       \
            u64 bv = (BPTR)[j * 32 + lane];                                 \
            _Pragma("unroll")                                               \
            for (int r = 0; r < RPW; r++) acc[j][r] = bv;                   \
        }                                                                   \
        const u64* wp = (WPTR) + lane;                                      \
        const float* hp = (HPTR);                                           \
        _Pragma("unroll 2")                                                 \
        for (int kq = 0; kq < (NQ); kq++) {                                 \
            float4 hq[RPW];                                                 \
            _Pragma("unroll")                                               \
            for (int r = 0; r < RPW; r++)                                   \
                hq[r] = *(const float4*)(hp + r * (HSTR) + kq * 4);         \
            _Pragma("unroll")                                               \
            for (int half = 0; half < 2; half++) {                         \
                u64 hpk[RPW];                                               \
                _Pragma("unroll")                                           \
                for (int r = 0; r < RPW; r++)                               \
                    hpk[r] = half ? pk2(hq[r].z, hq[r].w)                   \
                                  : pk2(hq[r].x, hq[r].y);                  \
                const u64* wrow = wp + (2 * kq + half) * G4;                \
                _Pragma("unroll")                                           \
                for (int j = 0; j < 7; j++) {                               \
                    u64 wv = wrow[j * 32];                                  \
                    _Pragma("unroll")                                       \
                    for (int r = 0; r < RPW; r++) fma2(acc[j][r], hpk[r], wv); \
                }                                                           \
            }                                                               \
        }                                                                   \
        _Pragma("unroll")                                                   \
        for (int j = 0; j < 7; j++) {                                       \
            int g = j * 32 + lane;                                          \
            if (g < G4) {                                                   \
                _Pragma("unroll")                                           \
                for (int r = 0; r < RPW; r++) {                             \
                    float2 v = upk2(acc[j][r]);                             \
                    gs_[r * G4 + g] = v.x + v.y;                            \
                }                                                           \
            }                                                               \
        }                                                                   \
    } while (0)

__global__ __launch_bounds__(256, 1)
void lstm2_kernel(const float* __restrict__ x,
                  const float* __restrict__ W_ih1, const float* __restrict__ W_hh1,
                  const float* __restrict__ b_ih1, const float* __restrict__ b_hh1,
                  const float* __restrict__ W_ih2, const float* __restrict__ W_hh2,
                  const float* __restrict__ b_ih2, const float* __restrict__ b_hh2,
                  const float* __restrict__ W_lin, const float* __restrict__ b_lin,
                  float* __restrict__ out)
{
    extern __shared__ Smem smem_raw[];
    Smem& sm = smem_raw[0];
    const int tid = threadIdx.x;

    // ---------- one-time smem setup ----------
    for (int idx = tid; idx < 26 * G4 + 32; idx += 256) {
        float a = 0.f, b = 0.f;
        if (idx < 26 * G4) {
            int kp = idx / G4, g = idx - kp * G4;
            int k0 = 2 * kp, k1 = 2 * kp + 1;
            a = (k0 < 51) ? W_hh1[g * NS + k0] : W_ih1[g];
            b = (k1 < 51) ? W_hh1[g * NS + k1] : W_ih1[g];
        }
        sm.Wp1[idx] = pk2(a, b);
    }
    for (int idx = tid; idx < 52 * G4 + 32; idx += 256) {
        float a = 0.f, b = 0.f;
        if (idx < 52 * G4) {
            int kp = idx / G4, g = idx - kp * G4;
            int k0 = 2 * kp, k1 = 2 * kp + 1;
            a = (k0 < 51) ? W_ih2[g * NS + k0]
              : (k0 >= 52 && k0 <= 102) ? W_hh2[g * NS + (k0 - 52)] : 0.f;
            b = (k1 < 51) ? W_ih2[g * NS + k1]
              : (k1 >= 52 && k1 <= 102) ? W_hh2[g * NS + (k1 - 52)] : 0.f;
        }
        sm.Wp2[idx] = pk2(a, b);
    }
    if (tid < 224) {
        float v1 = (tid < G4) ? b_ih1[tid] + b_hh1[tid] : 0.f;
        float v2 = (tid < G4) ? b_ih2[tid] + b_hh2[tid] : 0.f;
        sm.b1p[tid] = pk2(v1, 0.f);
        sm.b2p[tid] = pk2(v2, 0.f);
    }
    if (tid < 32) {
        float a = (2 * tid < NS) ? W_lin[2 * tid] : 0.f;
        float b = (2 * tid + 1 < NS) ? W_lin[2 * tid + 1] : 0.f;
        sm.wlinp[tid] = pk2(a, b);
    }
    {
        float* hz = &sm.hA[0][0][0];
        for (int idx = tid; idx < WARPS * RPW * (52 + 104); idx += 256) hz[idx] = 0.f;
    }
    __syncthreads();

    // ---------- per-thread setup ----------
    const int warp = tid >> 5, lane = tid & 31;
    float* __restrict__ hA_ = &sm.hA[warp][0][0];
    float* __restrict__ hB_ = &sm.hB[warp][0][0];
    float* __restrict__ gs_ = &sm.gs[warp][0][0];
    const int rbase = blockIdx.x * ROWS + warp * RPW;
    const int myrow = rbase + lane;
    const bool ok = (lane < RPW) && (myrow < BSZ);
    const float blin = b_lin[0];
    const float* xp = x + (size_t)myrow * TLEN;
    float* outp = out + (size_t)myrow * TLEN;

    float c1[NCELL], c2[NCELL];
#pragma unroll
    for (int i = 0; i < NCELL; i++) { c1[i] = 0.f; c2[i] = 0.f; }

    float xreg = ok ? xp[0] : 0.f;
    u64 acc[7][RPW];

    // ---------- time loop (warp-synchronous) ----------
    for (int t = 0; t < TLEN; t++) {
        if (lane < RPW) hA_[lane * 52 + 51] = xreg;
        __syncwarp();
        if (ok && t + 1 < TLEN) xreg = xp[t + 1];

        // ===== layer 1 =====
        GEMM_LAYER(KQ1, sm.Wp1, hA_, 52, sm.b1p);
        __syncwarp();
#pragma unroll
        for (int i = 0; i < NCELL; i++) {
            int cell = lane + 32 * i;
            if (cell < RPW * NS) {
                int r = cell / NS, n = cell - r * NS;
                const float* gr = gs_ + r * G4 + n;
                float iv = gr[0], fv = gr[51], gv = gr[102], ov = gr[153];
                float c = sigf(fv) * c1[i] + sigf(iv) * tanhf_(gv);
                c1[i] = c;
                float hnew = sigf(ov) * tanhf_(c);
                hA_[r * 52 + n] = hnew;   // next-step layer1 input
                hB_[r * 104 + n] = hnew;  // layer2 input
            }
        }
        __syncwarp();

        // ===== layer 2 =====
        GEMM_LAYER(KQ2, sm.Wp2, hB_, 104, sm.b2p);
        __syncwarp();
#pragma unroll
        for (int i = 0; i < NCELL; i++) {
            int cell = lane + 32 * i;
            if (cell < RPW * NS) {
                int r = cell / NS, n = cell - r * NS;
                const float* gr = gs_ + r * G4 + n;
                float iv = gr[0], fv = gr[51], gv = gr[102], ov = gr[153];
                float c = sigf(fv) * c2[i] + sigf(iv) * tanhf_(gv);
                c2[i] = c;
                hB_[r * 104 + 52 + n] = sigf(ov) * tanhf_(c);
            }
        }
        __syncwarp();

        // ===== output projection =====
        if (ok) {
            u64 y2 = pk2(blin, 0.f);
            const u64* h2p = (const u64*)(hB_ + lane * 104 + 52);
#pragma unroll
            for (int np = 0; np < 26; np++) fma2(y2, h2p[np], sm.wlinp[np]);
            float2 yy = upk2(y2);
            outp[t] = yy.x + yy.y;
        }
        __syncwarp();
    }
}

extern "C" void kernel_launch(void* const* d_in, const int* in_sizes, int n_in,
                              void* d_out, int out_size) {
    const float* x     = (const float*)d_in[0];
    const float* W_ih1 = (const float*)d_in[1];
    const float* W_hh1 = (const float*)d_in[2];
    const float* b_ih1 = (const float*)d_in[3];
    const float* b_hh1 = (const float*)d_in[4];
    const float* W_ih2 = (const float*)d_in[5];
    const float* W_hh2 = (const float*)d_in[6];
    const float* b_ih2 = (const float*)d_in[7];
    const float* b_hh2 = (const float*)d_in[8];
    const float* W_lin = (const float*)d_in[9];
    const float* b_lin = (const float*)d_in[10];
    float* out = (float*)d_out;

    cudaFuncSetAttribute(lstm2_kernel,
                         cudaFuncAttributeMaxDynamicSharedMemorySize,
                         (int)sizeof(Smem));
    lstm2_kernel<<<GRID, 256, sizeof(Smem)>>>(
        x, W_ih1, W_hh1, b_ih1, b_hh1,
        W_ih2, W_hh2, b_ih2, b_hh2,
        W_lin, b_lin, out);
}

// round 4
// speedup vs baseline: 2.6358x; 2.3710x over previous
#include <cuda_runtime.h>
#include <cstdint>

// 2-layer LSTM (NS=51), B=8192, T=2048, fp32 out [B,T].
// tf32 mma.sync.m16n8k8 implementation (plain sm_103-compatible PTX).
// 128 CTAs x 256 thr; CTA owns 64 batch rows.
// Unified A operand (K=112): k0..50 h1 | k51 x_t | k52 1.0 (bias col) | k53..103 h2 | pad.
// B (weights) pre-packed in fragment order; gate cols interleaved n=4*cell+q.
// L1 = k-chunks 0..6 vs B1; L2 = k-chunks 0..13 vs B2.

#define NS      51
#define TLEN    2048
#define MROWS   64
#define GRID    128
#define THREADS 256
#define NT      28      // n-tiles (N=224)
#define NTW     7       // n-tiles per warp
#define KC1     7
#define KC2     14

// smem offsets in u32 units
#define OFF_A   0                    // [14 kc][4 mt][32 lane][4]  = 7168 u32
#define OFF_B1  7168                 // [7 kc][28 nt][32 lane][2]  = 12544 u32
#define OFF_B2  19712                // [14][28][32][2]            = 25088 u32
#define OFF_YP  44800                // 64 rows x 8 partials (float)
#define SMEM_U32 45344
#define SMEM_BYTES (SMEM_U32*4)

__device__ __forceinline__ float sigf(float x){ return __fdividef(1.f, 1.f + __expf(-x)); }
__device__ __forceinline__ float tanhf_(float x){ return fmaf(2.f, sigf(2.f*x), -1.f); }
__device__ __forceinline__ uint32_t tf32c(float f){
    uint32_t r; asm("cvt.rna.tf32.f32 %0, %1;" : "=r"(r) : "f"(f)); return r;
}
__device__ __forceinline__ void mma8(float* d, const uint32_t* a, const uint32_t* b){
    asm volatile("mma.sync.aligned.m16n8k8.row.col.f32.tf32.tf32.f32 "
        "{%0,%1,%2,%3}, {%4,%5,%6,%7}, {%8,%9}, {%0,%1,%2,%3};"
        : "+f"(d[0]),"+f"(d[1]),"+f"(d[2]),"+f"(d[3])
        : "r"(a[0]),"r"(a[1]),"r"(a[2]),"r"(a[3]), "r"(b[0]),"r"(b[1]));
}

// weight element for B1/B2 fragment packing
__device__ __forceinline__ float wval1(int k, int n,
    const float* W_ih1, const float* W_hh1, const float* b_ih1, const float* b_hh1){
    int c = n >> 2, q = n & 3;
    if (c >= NS) return 0.f;
    int go = q*NS + c;
    if (k < NS)  return W_hh1[go*NS + k];
    if (k == NS) return W_ih1[go];
    if (k == NS+1) return b_ih1[go] + b_hh1[go];
    return 0.f;
}
__device__ __forceinline__ float wval2(int k, int n,
    const float* W_ih2, const float* W_hh2, const float* b_ih2, const float* b_hh2){
    int c = n >> 2, q = n & 3;
    if (c >= NS) return 0.f;
    int go = q*NS + c;
    if (k < NS)  return W_ih2[go*NS + k];
    if (k == NS+1) return b_ih2[go] + b_hh2[go];
    if (k >= 53 && k <= 103) return W_hh2[go*NS + (k-53)];
    return 0.f;
}

#define GEMM(KCN, BOFF) do {                                                   \
    _Pragma("unroll")                                                          \
    for (int mt_=0; mt_<2; mt_++)                                              \
        _Pragma("unroll")                                                      \
        for (int tl_=0; tl_<7; tl_++)                                          \
            _Pragma("unroll")                                                  \
            for (int q_=0; q_<4; q_++) acc[mt_][tl_][q_] = 0.f;                \
    _Pragma("unroll 2")                                                        \
    for (int kc=0; kc<(KCN); kc++){                                            \
        uint4 a0 = *(const uint4*)&smem_u[OFF_A + (kc*4 + 2*warpM  )*128 + lane*4]; \
        uint4 a1 = *(const uint4*)&smem_u[OFF_A + (kc*4 + 2*warpM+1)*128 + lane*4]; \
        uint2 bv[7];                                                           \
        _Pragma("unroll")                                                      \
        for (int tl=0; tl<7; tl++)                                             \
            bv[tl] = *(const uint2*)&smem_u[(BOFF) + (kc*NT + warpN*NTW + tl)*64 + lane*2]; \
        _Pragma("unroll")                                                      \
        for (int tl=0; tl<7; tl++){                                            \
            mma8(acc[0][tl], (const uint32_t*)&a0, (const uint32_t*)&bv[tl]);  \
            mma8(acc[1][tl], (const uint32_t*)&a1, (const uint32_t*)&bv[tl]);  \
        }                                                                      \
    }                                                                          \
} while(0)

// LAYER: 1 or 2
#define EPILOGUE(LAYER, CST, XV0, XV1) do {                                    \
    _Pragma("unroll")                                                          \
    for (int mt=0; mt<2; mt++){                                                \
        const int mtg = 2*warpM + mt;                                          \
        float ypa = 0.f;                                                       \
        _Pragma("unroll")                                                      \
        for (int tl=0; tl<7; tl++){                                            \
            float d0=acc[mt][tl][0], d1=acc[mt][tl][1];                        \
            float d2=acc[mt][tl][2], d3=acc[mt][tl][3];                        \
            float s0 = __shfl_xor_sync(0xffffffffu, odd ? d0 : d2, 1);         \
            float s1 = __shfl_xor_sync(0xffffffffu, odd ? d1 : d3, 1);         \
            float iv = odd ? s0 : d0;                                          \
            float fv = odd ? s1 : d1;                                          \
            float gv = odd ? d2 : s0;                                          \
            float ov = odd ? d3 : s1;                                          \
            float cc = sigf(fv)*(CST)[mt*7+tl] + sigf(iv)*tanhf_(gv);          \
            (CST)[mt*7+tl] = cc;                                               \
            float hh = sigf(ov)*tanhf_(cc);                                    \
            if ((LAYER)==2) ypa = fmaf(wlin_r[tl], hh, ypa);                   \
            int cell = (warpN*7 + tl)*2 + par;                                 \
            if (cell < NS){                                                    \
                int k = ((LAYER)==1) ? cell : (53 + cell);                     \
                int kc = k>>3, k8 = k&7;                                       \
                int idx = (kc*4+mtg)*128 + ((r16own&7)*4 + (k8&3))*4           \
                        + (k8>>2)*2 + p2;                                      \
                smem_u[OFF_A + idx] = tf32c(hh);                               \
            }                                                                  \
        }                                                                      \
        if ((LAYER)==1 && warpN==0 && (lane&3)<2){                             \
            int idx = (6*4+mtg)*128 + ((r16own&7)*4 + 3)*4 + p2;   /* k=51 */  \
            smem_u[OFF_A + idx] = tf32c(mt ? (XV1) : (XV0));                   \
        }                                                                      \
        if ((LAYER)==2)                                                        \
            smem_f[OFF_YP + (mtg*16 + r16own)*8 + warpN*2 + par] = ypa;        \
    }                                                                          \
} while(0)

__global__ __launch_bounds__(THREADS, 1)
void lstm2_mma(const float* __restrict__ x,
               const float* __restrict__ W_ih1, const float* __restrict__ W_hh1,
               const float* __restrict__ b_ih1, const float* __restrict__ b_hh1,
               const float* __restrict__ W_ih2, const float* __restrict__ W_hh2,
               const float* __restrict__ b_ih2, const float* __restrict__ b_hh2,
               const float* __restrict__ W_lin, const float* __restrict__ b_lin,
               float* __restrict__ out)
{
    extern __shared__ uint32_t smem_u[];
    float* smem_f = (float*)smem_u;
    const int tid = threadIdx.x;
    const int wid = tid >> 5, lane = tid & 31;
    const int warpN = wid & 3, warpM = wid >> 2;
    const int odd = lane & 1;
    const int par = (lane & 3) >> 1;                    // cell parity within tile
    const int r16own = (lane >> 2) + ((lane & 1) << 3); // row within 16-row m-tile
    const int p2 = r16own >> 3;
    const int row0 = blockIdx.x * MROWS;

    // ---------------- one-time init ----------------
    for (int idx = tid; idx < 7168; idx += THREADS) smem_u[OFF_A + idx] = 0;
    for (int idx = tid; idx < 7*NT*32; idx += THREADS){
        int kc = idx / (NT*32), rem = idx % (NT*32);
        int nt = rem >> 5, l2 = rem & 31;
        int k0 = kc*8 + (l2 & 3), n = nt*8 + (l2 >> 2);
        smem_u[OFF_B1 + idx*2    ] = tf32c(wval1(k0,   n, W_ih1, W_hh1, b_ih1, b_hh1));
        smem_u[OFF_B1 + idx*2 + 1] = tf32c(wval1(k0+4, n, W_ih1, W_hh1, b_ih1, b_hh1));
    }
    for (int idx = tid; idx < 14*NT*32; idx += THREADS){
        int kc = idx / (NT*32), rem = idx % (NT*32);
        int nt = rem >> 5, l2 = rem & 31;
        int k0 = kc*8 + (l2 & 3), n = nt*8 + (l2 >> 2);
        smem_u[OFF_B2 + idx*2    ] = tf32c(wval2(k0,   n, W_ih2, W_hh2, b_ih2, b_hh2));
        smem_u[OFF_B2 + idx*2 + 1] = tf32c(wval2(k0+4, n, W_ih2, W_hh2, b_ih2, b_hh2));
    }
    __syncthreads();
    if (tid < MROWS){
        int r16 = tid & 15, mtg = tid >> 4;
        // k=51 : x[row][0]
        int i51 = (6*4+mtg)*128 + ((r16&7)*4 + 3)*4 + (r16>>3);
        smem_u[OFF_A + i51] = tf32c(x[(size_t)(row0 + tid)*TLEN]);
        // k=52 : 1.0 (bias column)
        int i52 = (6*4+mtg)*128 + ((r16&7)*4 + 0)*4 + 2 + (r16>>3);
        smem_u[OFF_A + i52] = tf32c(1.0f);
    }

    // per-thread constants
    float wlin_r[7];
#pragma unroll
    for (int tl = 0; tl < 7; tl++){
        int cell = (warpN*7 + tl)*2 + par;
        wlin_r[tl] = (cell < NS) ? W_lin[cell] : 0.f;
    }
    const float blin = b_lin[0];
    float c1[14], c2[14];
#pragma unroll
    for (int i = 0; i < 14; i++){ c1[i] = 0.f; c2[i] = 0.f; }

    const int xrow0 = row0 + (2*warpM  )*16 + r16own;
    const int xrow1 = row0 + (2*warpM+1)*16 + r16own;
    const bool xldr = (warpN == 0) && ((lane & 3) < 2);

    float acc[2][7][4];
    __syncthreads();

    // ---------------- time loop ----------------
    for (int t = 0; t < TLEN; t++){
        float xv0 = 0.f, xv1 = 0.f;
        if (xldr && t + 1 < TLEN){
            xv0 = x[(size_t)xrow0*TLEN + t + 1];
            xv1 = x[(size_t)xrow1*TLEN + t + 1];
        }

        GEMM(KC1, OFF_B1);
        __syncthreads();               // all warps done reading A
        EPILOGUE(1, c1, xv0, xv1);     // writes h1new (k0..50) + x_{t+1} (k51)
        __syncthreads();

        GEMM(KC2, OFF_B2);
        __syncthreads();               // all warps done reading A
        EPILOGUE(2, c2, 0.f, 0.f);     // writes h2new (k53..103) + y partials
        __syncthreads();

        if (tid < MROWS){
            const float4 u = *(const float4*)&smem_f[OFF_YP + tid*8];
            const float4 v = *(const float4*)&smem_f[OFF_YP + tid*8 + 4];
            float y = u.x + u.y + u.z + u.w + v.x + v.y + v.z + v.w + blin;
            out[(size_t)(row0 + tid)*TLEN + t] = y;
        }
    }
}

extern "C" void kernel_launch(void* const* d_in, const int* in_sizes, int n_in,
                              void* d_out, int out_size) {
    const float* x     = (const float*)d_in[0];
    const float* W_ih1 = (const float*)d_in[1];
    const float* W_hh1 = (const float*)d_in[2];
    const float* b_ih1 = (const float*)d_in[3];
    const float* b_hh1 = (const float*)d_in[4];
    const float* W_ih2 = (const float*)d_in[5];
    const float* W_hh2 = (const float*)d_in[6];
    const float* b_ih2 = (const float*)d_in[7];
    const float* b_hh2 = (const float*)d_in[8];
    const float* W_lin = (const float*)d_in[9];
    const float* b_lin = (const float*)d_in[10];
    float* out = (float*)d_out;

    cudaFuncSetAttribute(lstm2_mma, cudaFuncAttributeMaxDynamicSharedMemorySize, SMEM_BYTES);
    lstm2_mma<<<GRID, THREADS, SMEM_BYTES>>>(
        x, W_ih1, W_hh1, b_ih1, b_hh1,
        W_ih2, W_hh2, b_ih2, b_hh2,
        W_lin, b_lin, out);
}